// round 7
// baseline (speedup 1.0000x reference)
#include <cuda_runtime.h>
#include <cuda_bf16.h>
#include <math.h>

#define NQ      32
#define DIM     128
#define TOPK    10
#define NBLK    592
#define TPB     128
#define SLOTS   64                 // candidates per (query, block) = 32 threads * 2
#define MCAND   (NBLK * SLOTS)     // 37888 per query
#define NRES    32                 // exactly-rescored candidates per query
#define NEG_INF (-3.402823466e38f)
#define MAGIC   12582912.0f        // 1.5 * 2^23
#define CSCALE  (127.0f / 6.6f)    // int8 scale; N(0,1) max over 1.28e8 samples ~6.1

// ---- static device scratch (no allocations allowed) ----
__device__ float g_qn[NQ * DIM];             // normalized queries, fp32 exact
__device__ int   g_q8[NQ * 32];              // packed int8 queries (canonical layout)
__device__ float g_psc[NBLK * NQ * SLOTS];   // per-block approx candidate scores
__device__ int   g_pix[NBLK * NQ * SLOTS];   // per-block candidate row indices

// ============================================================
// K1: normalize queries (matches reference eps) + int8 quantize/pack
// ============================================================
__global__ void k1_prep(const float* __restrict__ q) {
    int t = threadIdx.x;
    if (t >= NQ) return;
    const float* row = q + t * DIM;
    float ss = 0.f;
    for (int i = 0; i < DIM; i++) ss += row[i] * row[i];
    float inv = 1.f / fmaxf(sqrtf(ss), 1e-12f);
    float ma = 0.f;
    for (int i = 0; i < DIM; i++) {
        float v = row[i] * inv;
        g_qn[t * DIM + i] = v;
        ma = fmaxf(ma, fabsf(v));
    }
    float sc = 127.f / fmaxf(ma, 1e-12f);
    for (int g = 0; g < 32; g++) {
        int b[4];
        #pragma unroll
        for (int m = 0; m < 4; m++) {
            float f = fminf(fmaxf(row[g * 4 + m] * inv * sc, -127.f), 127.f) + MAGIC;
            b[m] = __float_as_int(f);   // low byte = rounded int8 (two's complement)
        }
        g_q8[t * 32 + g] = __byte_perm(__byte_perm(b[0], b[1], 0x0040),
                                       __byte_perm(b[2], b[3], 0x0040), 0x5410);
    }
}

// ============================================================
// K2: int8 dp4a corpus scan, per-(query,thread) top-2 across the block's rows
// ============================================================
__global__ void __launch_bounds__(TPB, 4)
k2_scan(const float* __restrict__ corpus, int N, int rpb) {
    __shared__ __align__(16) int   c8 [128 * 32]; // int8-packed tile, XOR-swizzled 16B groups
    __shared__ __align__(16) int   q8s[NQ * 32];  // packed queries, swizzled on q>>3
    __shared__ float rinv[128];                   // rsqrt(||c8_row||^2)

    const int tid = threadIdx.x;
    const int qg  = tid & 3;          // query group (8 queries)
    const int rg  = tid >> 2;         // row group (rows rg + 32*i)
    const int row0   = blockIdx.x * rpb;
    const int rowEnd = min(row0 + rpb, N);

    // stage queries with 16B-group swizzle: phys_group = gp ^ (q>>3)
    for (int i = tid; i < NQ * 32; i += TPB) {
        int q = i >> 5, k4 = i & 31;
        int gp = k4 >> 2, m = k4 & 3;
        int phys = (((gp ^ (q >> 3)) & 7) << 2) | m;
        q8s[q * 32 + phys] = g_q8[i];
    }

    float b1[8], b2[8];
    int   x1[8], x2[8];
    #pragma unroll
    for (int j = 0; j < 8; j++) { b1[j] = NEG_INF; b2[j] = NEG_INF; x1[j] = 0; x2[j] = 0; }

    const float4* gc = (const float4*)corpus;   // float4 index = row*32 + p

    for (int tb = row0; tb < rowEnd; tb += 128) {
        __syncthreads();   // protect c8/rinv from previous iteration's readers
        // ---- coalesced load + magic-FFMA int8 quantize + swizzled pack ----
        #pragma unroll
        for (int it = 0; it < 32; it++) {
            int li = it * TPB + tid;
            int r = li >> 5, p = li & 31;
            float4 v = make_float4(0.f, 0.f, 0.f, 0.f);
            if (tb + r < rowEnd) v = __ldg(&gc[(size_t)(tb + r) * 32 + p]);
            int i0 = __float_as_int(fmaf(v.x, CSCALE, MAGIC));
            int i1 = __float_as_int(fmaf(v.y, CSCALE, MAGIC));
            int i2 = __float_as_int(fmaf(v.z, CSCALE, MAGIC));
            int i3 = __float_as_int(fmaf(v.w, CSCALE, MAGIC));
            int pk = __byte_perm(__byte_perm(i0, i1, 0x0040),
                                 __byte_perm(i2, i3, 0x0040), 0x5410);
            int gp = p >> 2, m = p & 3;
            int phys = (((gp ^ (r & 7)) & 7) << 2) | m;
            c8[r * 32 + phys] = pk;
        }
        __syncthreads();
        // ---- per-row int8 norm ----
        {
            int r = tid;
            int nsq = 0;
            #pragma unroll
            for (int g = 0; g < 8; g++) {
                const int4 a = *(const int4*)&c8[r * 32 + (((g ^ (r & 7)) & 7) << 2)];
                nsq = __dp4a(a.x, a.x, nsq); nsq = __dp4a(a.y, a.y, nsq);
                nsq = __dp4a(a.z, a.z, nsq); nsq = __dp4a(a.w, a.w, nsq);
            }
            rinv[r] = rsqrtf((float)max(nsq, 1));
        }
        __syncthreads();

        // ---- register-tiled dp4a: 4 rows x 8 queries per thread ----
        int acc[4][8];
        #pragma unroll
        for (int i = 0; i < 4; i++)
            #pragma unroll
            for (int j = 0; j < 8; j++) acc[i][j] = 0;

        #pragma unroll
        for (int g = 0; g < 8; g++) {
            int4 cv[4];
            #pragma unroll
            for (int i = 0; i < 4; i++)
                cv[i] = *(const int4*)&c8[(rg + 32 * i) * 32 + (((g ^ (rg & 7)) & 7) << 2)];
            #pragma unroll
            for (int j = 0; j < 8; j++) {
                const int q = qg * 8 + j;
                const int4 qv = *(const int4*)&q8s[q * 32 + (((g ^ qg) & 7) << 2)];
                #pragma unroll
                for (int i = 0; i < 4; i++) {
                    acc[i][j] = __dp4a(cv[i].x, qv.x, acc[i][j]);
                    acc[i][j] = __dp4a(cv[i].y, qv.y, acc[i][j]);
                    acc[i][j] = __dp4a(cv[i].z, qv.z, acc[i][j]);
                    acc[i][j] = __dp4a(cv[i].w, qv.w, acc[i][j]);
                }
            }
        }

        // ---- per-(query,thread) top-2 update ----
        #pragma unroll
        for (int i = 0; i < 4; i++) {
            int row = tb + rg + 32 * i;
            if (row < rowEnd) {
                float ri = rinv[rg + 32 * i];
                #pragma unroll
                for (int j = 0; j < 8; j++) {
                    float s = (float)acc[i][j] * ri;
                    if (s > b1[j]) { b2[j] = b1[j]; x2[j] = x1[j]; b1[j] = s; x1[j] = row; }
                    else if (s > b2[j]) { b2[j] = s; x2[j] = row; }
                }
            }
        }
    }

    // ---- write candidates (unconditionally, deterministic each launch) ----
    #pragma unroll
    for (int j = 0; j < 8; j++) {
        int q = qg * 8 + j;
        int base = (blockIdx.x * NQ + q) * SLOTS + rg * 2;
        g_psc[base]     = b1[j];  g_psc[base + 1] = b2[j];
        g_pix[base]     = x1[j];  g_pix[base + 1] = x2[j];
    }
}

// ============================================================
// K3: per-query merge (top-4/thread -> 1024 pool -> 32 argmax rounds),
//     exact fp32 rescore, rank-based top-10 with jax tie-break
// ============================================================
__global__ void __launch_bounds__(256, 1)
k3_merge(const float* __restrict__ corpus, float* __restrict__ out, int N) {
    __shared__ float cs[1024];
    __shared__ int   ci[1024];
    __shared__ __align__(16) float qn_s[DIM];
    __shared__ float red_s[8];
    __shared__ int   red_p[8];
    __shared__ float rs[NRES];
    __shared__ int   rix[NRES];

    const int q = blockIdx.x;
    const int t = threadIdx.x;

    if (t < DIM) qn_s[t] = g_qn[q * DIM + t];

    // top-4 per thread over strided candidate slice
    float b[4]  = {NEG_INF, NEG_INF, NEG_INF, NEG_INF};
    int   bx[4] = {0, 0, 0, 0};
    for (int c = t; c < MCAND; c += 256) {
        int blk = c >> 6, slot = c & 63;
        int addr = (blk * NQ + q) * SLOTS + slot;
        float s = g_psc[addr];
        if (s > b[3]) {
            int id = g_pix[addr];
            if (s > b[0]) { b[3]=b[2]; bx[3]=bx[2]; b[2]=b[1]; bx[2]=bx[1]; b[1]=b[0]; bx[1]=bx[0]; b[0]=s; bx[0]=id; }
            else if (s > b[1]) { b[3]=b[2]; bx[3]=bx[2]; b[2]=b[1]; bx[2]=bx[1]; b[1]=s; bx[1]=id; }
            else if (s > b[2]) { b[3]=b[2]; bx[3]=bx[2]; b[2]=s; bx[2]=id; }
            else               { b[3]=s; bx[3]=id; }
        }
    }
    #pragma unroll
    for (int k = 0; k < 4; k++) { cs[t * 4 + k] = b[k]; ci[t * 4 + k] = bx[k]; }
    __syncthreads();

    // 32 argmax-and-invalidate rounds over the 1024-entry pool
    for (int r = 0; r < NRES; r++) {
        float mv = NEG_INF; int mp = 0;
        #pragma unroll
        for (int k = 0; k < 4; k++) {
            float v = cs[t * 4 + k];
            if (v > mv) { mv = v; mp = t * 4 + k; }
        }
        #pragma unroll
        for (int o = 16; o > 0; o >>= 1) {
            float ov = __shfl_down_sync(0xffffffffu, mv, o);
            int   op = __shfl_down_sync(0xffffffffu, mp, o);
            if (ov > mv) { mv = ov; mp = op; }
        }
        if ((t & 31) == 0) { red_s[t >> 5] = mv; red_p[t >> 5] = mp; }
        __syncthreads();
        if (t == 0) {
            float wv = red_s[0]; int wp = red_p[0];
            #pragma unroll
            for (int w = 1; w < 8; w++)
                if (red_s[w] > wv) { wv = red_s[w]; wp = red_p[w]; }
            rix[r] = ci[wp];
            cs[wp] = NEG_INF;
        }
        __syncthreads();
    }

    // exact fp32 rescore: warp w handles candidates w, w+8, w+16, w+24
    const int w = t >> 5, l = t & 31;
    for (int c = w; c < NRES; c += 8) {
        int idx = rix[c];
        const float4 cv = __ldg(&((const float4*)corpus)[(size_t)idx * 32 + l]);
        float4 qv = *(const float4*)&qn_s[l * 4];
        float dot = cv.x * qv.x + cv.y * qv.y + cv.z * qv.z + cv.w * qv.w;
        float n2  = cv.x * cv.x + cv.y * cv.y + cv.z * cv.z + cv.w * cv.w;
        #pragma unroll
        for (int o = 16; o > 0; o >>= 1) {
            dot += __shfl_down_sync(0xffffffffu, dot, o);
            n2  += __shfl_down_sync(0xffffffffu, n2,  o);
        }
        if (l == 0) rs[c] = dot / fmaxf(sqrtf(n2), 1e-12f);
    }
    __syncthreads();

    // rank each of 32 candidates; ties broken by lower index (jax.lax.top_k)
    if (t < NRES) {
        float s = rs[t]; int id = rix[t];
        int rank = 0;
        for (int jj = 0; jj < NRES; jj++) {
            float so = rs[jj]; int io = rix[jj];
            if (so > s || (so == s && io < id)) rank++;
        }
        if (rank < TOPK) {
            out[q * TOPK + rank]             = s;          // top_scores [32,10]
            out[NQ * TOPK + q * TOPK + rank] = (float)id;  // top_idx    [32,10]
        }
    }
}

extern "C" void kernel_launch(void* const* d_in, const int* in_sizes, int n_in,
                              void* d_out, int out_size) {
    const float* queries = (const float*)d_in[0];
    const float* corpus  = (const float*)d_in[1];
    int N   = in_sizes[1] / DIM;
    int rpb = (N + NBLK - 1) / NBLK;
    k1_prep<<<1, 32>>>(queries);
    k2_scan<<<NBLK, TPB>>>(corpus, N, rpb);
    k3_merge<<<NQ, 256>>>(corpus, (float*)d_out, N);
}